// round 1
// baseline (speedup 1.0000x reference)
#include <cuda_runtime.h>
#include <math.h>

#define TOKENS 4096
#define DIM    2048
#define NEXP   32
#define TOPK   8
#define MDIM   768
#define NROWS  (TOKENS*TOPK)
#define BM     128
#define MAX_TILES 288   // <= 32768/128 + 32

// ---------------- device scratch (static, allocation-free) ----------------
__device__ int   g_cnt[NEXP];
__device__ int   g_off[NEXP + 1];
__device__ int   g_cursor[NEXP];
__device__ int   g_expert_of[NROWS];
__device__ float g_weight_of[NROWS];
__device__ int   g_row_token[NROWS];   // sorted row -> source token
__device__ int   g_pos_of[NROWS];      // (t*8+k) -> sorted row
__device__ int   g_tile_expert[MAX_TILES];
__device__ int   g_tile_row[MAX_TILES];
__device__ int   g_num_tiles;
__device__ float g_inter[(size_t)NROWS * MDIM];   // ~100 MB
__device__ float g_eout[(size_t)NROWS * DIM];     // ~268 MB

// ---------------- init ----------------
__global__ void k_init() {
    int i = threadIdx.x;
    if (i < NEXP) { g_cnt[i] = 0; g_cursor[i] = 0; }
}

// ---------------- router: logits GEMM + top-8 + softmax ----------------
__global__ __launch_bounds__(256) void k_router(const float* __restrict__ x,
                                                const float* __restrict__ gk) {
    __shared__ float xs[64][64];   // 16 KB: 64 tokens x 64 dims
    __shared__ float gs[64][32];   // 8 KB : 64 dims x 32 experts
    __shared__ float lg[64][32];   // 8 KB : logits

    int tid = threadIdx.x;
    int t0  = blockIdx.x * 64;
    int e   = tid & 31;
    int r8  = tid >> 5;          // 0..7

    float acc[8];
#pragma unroll
    for (int i = 0; i < 8; i++) acc[i] = 0.f;

    for (int d0 = 0; d0 < DIM; d0 += 64) {
#pragma unroll
        for (int i = 0; i < 4; i++) {
            int f = tid + i * 256;
            int row = f >> 4, dv = f & 15;
            float4 v = *(const float4*)(x + (size_t)(t0 + row) * DIM + d0 + dv * 4);
            *(float4*)&xs[row][dv * 4] = v;
        }
#pragma unroll
        for (int i = 0; i < 2; i++) {
            int f = tid + i * 256;
            int dd = f >> 3, ev = f & 7;
            float4 v = *(const float4*)(gk + (size_t)(d0 + dd) * NEXP + ev * 4);
            *(float4*)&gs[dd][ev * 4] = v;
        }
        __syncthreads();
#pragma unroll 8
        for (int dd = 0; dd < 64; dd++) {
            float g = gs[dd][e];
#pragma unroll
            for (int rr = 0; rr < 8; rr++)
                acc[rr] += xs[rr * 8 + r8][dd] * g;
        }
        __syncthreads();
    }
#pragma unroll
    for (int rr = 0; rr < 8; rr++) lg[rr * 8 + r8][e] = acc[rr];
    __syncthreads();

    // top-8 selection + softmax over selected (== softmax->topk->renorm)
    int w = tid >> 5, lane = tid & 31;
    for (int ti = 0; ti < 8; ti++) {
        int tok = w * 8 + ti;
        float logit = lg[tok][lane];
        unsigned selmask = 0;
        float vals[TOPK]; int ids[TOPK];
#pragma unroll
        for (int k = 0; k < TOPK; k++) {
            float v = ((selmask >> lane) & 1u) ? -1e30f : logit;
            float bv = v; int bi = lane;
#pragma unroll
            for (int off = 16; off; off >>= 1) {
                float ov = __shfl_down_sync(0xffffffffu, bv, off);
                int   oi = __shfl_down_sync(0xffffffffu, bi, off);
                if (ov > bv || (ov == bv && oi < bi)) { bv = ov; bi = oi; }
            }
            bv = __shfl_sync(0xffffffffu, bv, 0);
            bi = __shfl_sync(0xffffffffu, bi, 0);
            vals[k] = bv; ids[k] = bi;
            selmask |= 1u << bi;
        }
        if (lane == 0) {
            float mx = vals[0], s = 0.f, wv[TOPK];
#pragma unroll
            for (int k = 0; k < TOPK; k++) { wv[k] = expf(vals[k] - mx); s += wv[k]; }
            float inv = 1.f / s;
            int t = t0 + tok;
#pragma unroll
            for (int k = 0; k < TOPK; k++) {
                g_weight_of[t * TOPK + k] = wv[k] * inv;
                g_expert_of[t * TOPK + k] = ids[k];
                atomicAdd(&g_cnt[ids[k]], 1);
            }
        }
    }
}

// ---------------- prefix sum + tile map ----------------
__global__ void k_prefix() {
    int lane = threadIdx.x;
    int c = (lane < NEXP) ? g_cnt[lane] : 0;
    int s = c;
#pragma unroll
    for (int off = 1; off < 32; off <<= 1) {
        int v = __shfl_up_sync(0xffffffffu, s, off);
        if (lane >= off) s += v;
    }
    if (lane < NEXP) g_off[lane + 1] = s;
    if (lane == 0) {
        g_off[0] = 0;
        int nt = 0, base = 0;
        for (int e = 0; e < NEXP; e++) {
            int cc = g_cnt[e];
            for (int r = 0; r < cc; r += BM) {
                g_tile_expert[nt] = e;
                g_tile_row[nt]    = base + r;
                nt++;
            }
            base += cc;
        }
        g_num_tiles = nt;
    }
}

// ---------------- scatter ----------------
__global__ void k_scatter() {
    int i = blockIdx.x * blockDim.x + threadIdx.x;
    if (i >= NROWS) return;
    int e = g_expert_of[i];
    int p = g_off[e] + atomicAdd(&g_cursor[e], 1);
    g_row_token[p] = i >> 3;
    g_pos_of[i] = p;
}

// ---------------- fused gate/up GEMM + SiLU ----------------
// C tile 128x64, BK=16; thread computes 8x4 outputs for both gate and up.
__global__ __launch_bounds__(256, 2) void k_gemm_gateup(const float* __restrict__ x,
                                                        const float* __restrict__ Wg,
                                                        const float* __restrict__ Wu) {
    int mt = blockIdx.x;
    if (mt >= g_num_tiles) return;
    int e       = g_tile_expert[mt];
    int row0    = g_tile_row[mt];
    int row_end = g_off[e + 1];
    int n0      = blockIdx.y * 64;

    __shared__ float As[16][BM];   // transposed A, 8 KB
    __shared__ float Bg[16][64];   // 4 KB
    __shared__ float Bu[16][64];   // 4 KB

    int tid = threadIdx.x;
    int tx = tid & 15, ty = tid >> 4;

    float accg[8][4], accu[8][4];
#pragma unroll
    for (int i = 0; i < 8; i++)
#pragma unroll
        for (int j = 0; j < 4; j++) { accg[i][j] = 0.f; accu[i][j] = 0.f; }

    // A-load mapping: (arow, kv); each thread loads rows arow and arow+64
    int arow = tid >> 2, kv = tid & 3;
    int rg0 = row0 + arow, rg1 = row0 + arow + 64;
    bool a0ok = rg0 < row_end, a1ok = rg1 < row_end;
    int tokA0 = a0ok ? g_row_token[rg0] : 0;
    int tokA1 = a1ok ? g_row_token[rg1] : 0;

    const float* wgb = Wg + (size_t)e * DIM * MDIM;
    const float* wub = Wu + (size_t)e * DIM * MDIM;
    int bk = tid >> 4, nv = tid & 15;   // B: (bk in 0..15, nv in 0..15)

    for (int k0 = 0; k0 < DIM; k0 += 16) {
        float4 a0 = a0ok ? *(const float4*)(x + (size_t)tokA0 * DIM + k0 + kv * 4)
                         : make_float4(0.f, 0.f, 0.f, 0.f);
        float4 a1 = a1ok ? *(const float4*)(x + (size_t)tokA1 * DIM + k0 + kv * 4)
                         : make_float4(0.f, 0.f, 0.f, 0.f);
        float4 bg = *(const float4*)(wgb + (size_t)(k0 + bk) * MDIM + n0 + nv * 4);
        float4 bu = *(const float4*)(wub + (size_t)(k0 + bk) * MDIM + n0 + nv * 4);
        __syncthreads();
        As[kv * 4 + 0][arow] = a0.x; As[kv * 4 + 1][arow] = a0.y;
        As[kv * 4 + 2][arow] = a0.z; As[kv * 4 + 3][arow] = a0.w;
        As[kv * 4 + 0][arow + 64] = a1.x; As[kv * 4 + 1][arow + 64] = a1.y;
        As[kv * 4 + 2][arow + 64] = a1.z; As[kv * 4 + 3][arow + 64] = a1.w;
        *(float4*)&Bg[bk][nv * 4] = bg;
        *(float4*)&Bu[bk][nv * 4] = bu;
        __syncthreads();
#pragma unroll
        for (int kk = 0; kk < 16; kk++) {
            float a[8];
            *(float4*)&a[0] = *(float4*)&As[kk][ty * 8];
            *(float4*)&a[4] = *(float4*)&As[kk][ty * 8 + 4];
            float4 b4g = *(float4*)&Bg[kk][tx * 4];
            float4 b4u = *(float4*)&Bu[kk][tx * 4];
            float bgv[4] = { b4g.x, b4g.y, b4g.z, b4g.w };
            float buv[4] = { b4u.x, b4u.y, b4u.z, b4u.w };
#pragma unroll
            for (int i = 0; i < 8; i++)
#pragma unroll
                for (int j = 0; j < 4; j++) {
                    accg[i][j] += a[i] * bgv[j];
                    accu[i][j] += a[i] * buv[j];
                }
        }
    }

#pragma unroll
    for (int i = 0; i < 8; i++) {
        int r = row0 + ty * 8 + i;
        if (r < row_end) {
            float4 o;
            float g, u;
            g = accg[i][0]; u = accu[i][0]; o.x = (g / (1.f + expf(-g))) * u;
            g = accg[i][1]; u = accu[i][1]; o.y = (g / (1.f + expf(-g))) * u;
            g = accg[i][2]; u = accu[i][2]; o.z = (g / (1.f + expf(-g))) * u;
            g = accg[i][3]; u = accu[i][3]; o.w = (g / (1.f + expf(-g))) * u;
            *(float4*)(g_inter + (size_t)r * MDIM + n0 + tx * 4) = o;
        }
    }
}

// ---------------- down GEMM ----------------
__global__ __launch_bounds__(256, 2) void k_gemm_down(const float* __restrict__ Wd) {
    int mt = blockIdx.x;
    if (mt >= g_num_tiles) return;
    int e       = g_tile_expert[mt];
    int row0    = g_tile_row[mt];
    int row_end = g_off[e + 1];
    int n0      = blockIdx.y * 64;

    __shared__ float As[16][BM];
    __shared__ float Bs[16][64];

    int tid = threadIdx.x;
    int tx = tid & 15, ty = tid >> 4;

    float acc[8][4];
#pragma unroll
    for (int i = 0; i < 8; i++)
#pragma unroll
        for (int j = 0; j < 4; j++) acc[i][j] = 0.f;

    int arow = tid >> 2, kv = tid & 3;
    int rg0 = row0 + arow, rg1 = row0 + arow + 64;
    bool a0ok = rg0 < row_end, a1ok = rg1 < row_end;
    const float* wdb = Wd + (size_t)e * MDIM * DIM;
    int bk = tid >> 4, nv = tid & 15;

    for (int k0 = 0; k0 < MDIM; k0 += 16) {
        float4 a0 = a0ok ? *(const float4*)(g_inter + (size_t)rg0 * MDIM + k0 + kv * 4)
                         : make_float4(0.f, 0.f, 0.f, 0.f);
        float4 a1 = a1ok ? *(const float4*)(g_inter + (size_t)rg1 * MDIM + k0 + kv * 4)
                         : make_float4(0.f, 0.f, 0.f, 0.f);
        float4 bb = *(const float4*)(wdb + (size_t)(k0 + bk) * DIM + n0 + nv * 4);
        __syncthreads();
        As[kv * 4 + 0][arow] = a0.x; As[kv * 4 + 1][arow] = a0.y;
        As[kv * 4 + 2][arow] = a0.z; As[kv * 4 + 3][arow] = a0.w;
        As[kv * 4 + 0][arow + 64] = a1.x; As[kv * 4 + 1][arow + 64] = a1.y;
        As[kv * 4 + 2][arow + 64] = a1.z; As[kv * 4 + 3][arow + 64] = a1.w;
        *(float4*)&Bs[bk][nv * 4] = bb;
        __syncthreads();
#pragma unroll
        for (int kk = 0; kk < 16; kk++) {
            float a[8];
            *(float4*)&a[0] = *(float4*)&As[kk][ty * 8];
            *(float4*)&a[4] = *(float4*)&As[kk][ty * 8 + 4];
            float4 b4 = *(float4*)&Bs[kk][tx * 4];
            float bv[4] = { b4.x, b4.y, b4.z, b4.w };
#pragma unroll
            for (int i = 0; i < 8; i++)
#pragma unroll
                for (int j = 0; j < 4; j++)
                    acc[i][j] += a[i] * bv[j];
        }
    }

#pragma unroll
    for (int i = 0; i < 8; i++) {
        int r = row0 + ty * 8 + i;
        if (r < row_end) {
            float4 o = make_float4(acc[i][0], acc[i][1], acc[i][2], acc[i][3]);
            *(float4*)(g_eout + (size_t)r * DIM + n0 + tx * 4) = o;
        }
    }
}

// ---------------- combine ----------------
__global__ __launch_bounds__(256) void k_combine(float* __restrict__ out) {
    int t = blockIdx.x;
    __shared__ float w[TOPK];
    __shared__ int   ps[TOPK];
    if (threadIdx.x < TOPK) {
        w[threadIdx.x]  = g_weight_of[t * TOPK + threadIdx.x];
        ps[threadIdx.x] = g_pos_of[t * TOPK + threadIdx.x];
    }
    __syncthreads();
    for (int d = threadIdx.x; d < DIM; d += 256) {
        float s = 0.f;
#pragma unroll
        for (int k = 0; k < TOPK; k++)
            s += w[k] * g_eout[(size_t)ps[k] * DIM + d];
        out[(size_t)t * DIM + d] = s;
    }
}

// ---------------- launch ----------------
extern "C" void kernel_launch(void* const* d_in, const int* in_sizes, int n_in,
                              void* d_out, int out_size) {
    const float* x  = (const float*)d_in[0];  // hidden_states [4,1024,2048]
    const float* gk = (const float*)d_in[1];  // gate_kernel   [2048,32]
    const float* wg = (const float*)d_in[2];  // gate_proj     [32,2048,768]
    const float* wu = (const float*)d_in[3];  // up_proj       [32,2048,768]
    const float* wd = (const float*)d_in[4];  // down_proj     [32,768,2048]
    float* out = (float*)d_out;

    k_init<<<1, 32>>>();
    k_router<<<TOKENS / 64, 256>>>(x, gk);
    k_prefix<<<1, 32>>>();
    k_scatter<<<NROWS / 256, 256>>>();
    dim3 g1(MAX_TILES, MDIM / 64);
    k_gemm_gateup<<<g1, 256>>>(x, wg, wu);
    dim3 g2(MAX_TILES, DIM / 64);
    k_gemm_down<<<g2, 256>>>(wd);
    k_combine<<<TOKENS, 256>>>(out);
}

// round 7
// speedup vs baseline: 1.2803x; 1.2803x over previous
#include <cuda_runtime.h>
#include <cuda_bf16.h>
#include <stdint.h>
#include <math.h>

#define TOKENS 4096
#define DIM    2048
#define NEXP   32
#define TOPK   8
#define MDIM   768
#define NROWS  (TOKENS*TOPK)
#define BM     128
#define MAX_TILES 288

__device__ __forceinline__ uint32_t smem_u32(const void* p) {
    uint32_t a;
    asm("{ .reg .u64 t; cvta.to.shared.u64 t, %1; cvt.u32.u64 %0, t; }" : "=r"(a) : "l"(p));
    return a;
}
__device__ __forceinline__ void cpasync16(uint32_t s, const void* g) {
    asm volatile("cp.async.cg.shared.global [%0], [%1], 16;" :: "r"(s), "l"(g) : "memory");
}
#define CP_COMMIT() asm volatile("cp.async.commit_group;" ::: "memory")
#define CP_WAIT0()  asm volatile("cp.async.wait_group 0;" ::: "memory")

#define LDSM4(r, addr) \
    asm volatile("ldmatrix.sync.aligned.m8n8.x4.shared.b16 {%0,%1,%2,%3}, [%4];" \
        : "=r"((r)[0]), "=r"((r)[1]), "=r"((r)[2]), "=r"((r)[3]) : "r"(addr))

#define MMA_BF16(d, a, b0v, b1v) \
    asm volatile("mma.sync.aligned.m16n8k16.row.col.f32.bf16.bf16.f32 " \
        "{%0,%1,%2,%3},{%4,%5,%6,%7},{%8,%9},{%0,%1,%2,%3};" \
        : "+f"((d)[0]), "+f"((d)[1]), "+f"((d)[2]), "+f"((d)[3]) \
        : "r"((a)[0]), "r"((a)[1]), "r"((a)[2]), "r"((a)[3]), "r"(b0v), "r"(b1v))

// 8 MMAs: two A row-halves x four n-groups (b covers n0-15, b2 covers n16-31)
#define MMA8(acc, A0, A1, b, b2) do { \
    MMA_BF16(acc[0][0],A0,(b)[0],(b)[1]);  MMA_BF16(acc[0][1],A0,(b)[2],(b)[3]);  \
    MMA_BF16(acc[0][2],A0,(b2)[0],(b2)[1]);MMA_BF16(acc[0][3],A0,(b2)[2],(b2)[3]);\
    MMA_BF16(acc[1][0],A1,(b)[0],(b)[1]);  MMA_BF16(acc[1][1],A1,(b)[2],(b)[3]);  \
    MMA_BF16(acc[1][2],A1,(b2)[0],(b2)[1]);MMA_BF16(acc[1][3],A1,(b2)[2],(b2)[3]);\
} while(0)

__device__ __forceinline__ void split2(float v, __nv_bfloat16& h, __nv_bfloat16& l) {
    h = __float2bfloat16(v);
    l = __float2bfloat16(v - __bfloat162float(h));
}
__device__ __forceinline__ uint32_t pack2(__nv_bfloat16 a, __nv_bfloat16 b) {
    __nv_bfloat162 t(a, b);
    return *(uint32_t*)&t;
}

// ============ device scratch (~402MB) ============
__device__ int   g_cnt[NEXP];
__device__ int   g_off[NEXP + 1];
__device__ int   g_cursor[NEXP];
__device__ int   g_expert_of[NROWS];
__device__ float g_weight_of[NROWS];
__device__ int   g_row_token[NROWS];
__device__ int   g_pos_of[NROWS];
__device__ int   g_tile_expert[MAX_TILES];
__device__ int   g_tile_row[MAX_TILES];
__device__ int   g_num_tiles;
__device__ __nv_bfloat16 g_Xh[(size_t)TOKENS * DIM];
__device__ __nv_bfloat16 g_Xl[(size_t)TOKENS * DIM];
__device__ __nv_bfloat16 g_Ih[(size_t)NROWS * MDIM];
__device__ __nv_bfloat16 g_Il[(size_t)NROWS * MDIM];
__device__ float g_eout[(size_t)NROWS * DIM];

// ============ routing (R1-proven) ============
__global__ void k_init() {
    int i = threadIdx.x;
    if (i < NEXP) { g_cnt[i] = 0; g_cursor[i] = 0; }
}

__global__ __launch_bounds__(256) void k_router(const float* __restrict__ x,
                                                const float* __restrict__ gk) {
    __shared__ float xs[64][64];
    __shared__ float gs[64][32];
    __shared__ float lg[64][32];
    int tid = threadIdx.x, t0 = blockIdx.x * 64, e = tid & 31, r8 = tid >> 5;
    float acc[8];
#pragma unroll
    for (int i = 0; i < 8; i++) acc[i] = 0.f;
    for (int d0 = 0; d0 < DIM; d0 += 64) {
#pragma unroll
        for (int i = 0; i < 4; i++) {
            int f = tid + i * 256, row = f >> 4, dv = f & 15;
            *(float4*)&xs[row][dv * 4] =
                *(const float4*)(x + (size_t)(t0 + row) * DIM + d0 + dv * 4);
        }
#pragma unroll
        for (int i = 0; i < 2; i++) {
            int f = tid + i * 256, dd = f >> 3, ev = f & 7;
            *(float4*)&gs[dd][ev * 4] =
                *(const float4*)(gk + (size_t)(d0 + dd) * NEXP + ev * 4);
        }
        __syncthreads();
#pragma unroll 8
        for (int dd = 0; dd < 64; dd++) {
            float g = gs[dd][e];
#pragma unroll
            for (int rr = 0; rr < 8; rr++) acc[rr] += xs[rr * 8 + r8][dd] * g;
        }
        __syncthreads();
    }
#pragma unroll
    for (int rr = 0; rr < 8; rr++) lg[rr * 8 + r8][e] = acc[rr];
    __syncthreads();

    int w = tid >> 5, lane = tid & 31;
    for (int ti = 0; ti < 8; ti++) {
        int tok = w * 8 + ti;
        float logit = lg[tok][lane];
        unsigned selmask = 0;
        float vals[TOPK]; int ids[TOPK];
#pragma unroll
        for (int k = 0; k < TOPK; k++) {
            float v = ((selmask >> lane) & 1u) ? -1e30f : logit;
            float bv = v; int bi = lane;
#pragma unroll
            for (int off = 16; off; off >>= 1) {
                float ov = __shfl_down_sync(0xffffffffu, bv, off);
                int   oi = __shfl_down_sync(0xffffffffu, bi, off);
                if (ov > bv || (ov == bv && oi < bi)) { bv = ov; bi = oi; }
            }
            bv = __shfl_sync(0xffffffffu, bv, 0);
            bi = __shfl_sync(0xffffffffu, bi, 0);
            vals[k] = bv; ids[k] = bi;
            selmask |= 1u << bi;
        }
        if (lane == 0) {
            float mx = vals[0], s = 0.f, wv[TOPK];
#pragma unroll
            for (int k = 0; k < TOPK; k++) { wv[k] = expf(vals[k] - mx); s += wv[k]; }
            float inv = 1.f / s;
            int t = t0 + tok;
#pragma unroll
            for (int k = 0; k < TOPK; k++) {
                g_weight_of[t * TOPK + k] = wv[k] * inv;
                g_expert_of[t * TOPK + k] = ids[k];
                atomicAdd(&g_cnt[ids[k]], 1);
            }
        }
    }
}

__global__ void k_prefix() {
    int lane = threadIdx.x;
    int c = (lane < NEXP) ? g_cnt[lane] : 0;
    int s = c;
#pragma unroll
    for (int off = 1; off < 32; off <<= 1) {
        int v = __shfl_up_sync(0xffffffffu, s, off);
        if (lane >= off) s += v;
    }
    if (lane < NEXP) g_off[lane + 1] = s;
    if (lane == 0) {
        g_off[0] = 0;
        int nt = 0, base = 0;
        for (int e = 0; e < NEXP; e++) {
            int cc = g_cnt[e];
            for (int r = 0; r < cc; r += BM) {
                g_tile_expert[nt] = e;
                g_tile_row[nt] = base + r;
                nt++;
            }
            base += cc;
        }
        g_num_tiles = nt;
    }
}

__global__ void k_scatter() {
    int i = blockIdx.x * blockDim.x + threadIdx.x;
    if (i >= NROWS) return;
    int e = g_expert_of[i];
    int p = g_off[e] + atomicAdd(&g_cursor[e], 1);
    g_row_token[p] = i >> 3;
    g_pos_of[i] = p;
}

// ============ token fp32 -> split bf16 ============
__global__ __launch_bounds__(256) void k_convert_x(const float* __restrict__ x) {
    int t = blockIdx.x;
    const float4* src = (const float4*)(x + (size_t)t * DIM);
#pragma unroll
    for (int i = 0; i < 2; i++) {
        int idx = threadIdx.x + i * 256;
        float4 v = src[idx];
        __nv_bfloat16 h0, h1, h2, h3, l0, l1, l2, l3;
        split2(v.x, h0, l0); split2(v.y, h1, l1);
        split2(v.z, h2, l2); split2(v.w, h3, l3);
        *(uint2*)(g_Xh + (size_t)t * DIM + idx * 4) = make_uint2(pack2(h0, h1), pack2(h2, h3));
        *(uint2*)(g_Xl + (size_t)t * DIM + idx * 4) = make_uint2(pack2(l0, l1), pack2(l2, l3));
    }
}

// ============ GEMM1: gate+up, on-the-fly W convert ============
__global__ __launch_bounds__(256) void k_gemm1(const float* __restrict__ Wg,
                                               const float* __restrict__ Wu) {
    int mt = blockIdx.y;
    if (mt >= g_num_tiles) return;
    int e = g_tile_expert[mt], row0 = g_tile_row[mt], row_end = g_off[e + 1];
    int n0 = blockIdx.x * 64;

    __shared__ __align__(128) char smem[45056];
    uint32_t sb = smem_u32(smem);
    int tid = threadIdx.x, wid = tid >> 5, lane = tid & 31;
    int wm0 = (wid >> 1) * 32, wn0 = (wid & 1) * 32;

    const __nv_bfloat16* gA[2]; uint32_t soA[2];
#pragma unroll
    for (int i = 0; i < 2; i++) {
        int c = tid + i * 256;
        int half = c >> 8, rem = c & 255, row = rem >> 1, q = rem & 1;
        int gr = row0 + row; if (gr > NROWS - 1) gr = NROWS - 1;
        int tok = g_row_token[gr];
        gA[i] = (half ? g_Xl : g_Xh) + (size_t)tok * DIM + q * 8;
        soA[i] = half * 6144 + row * 48 + q * 16;
    }
    const float* gW[2]; uint32_t soW[2]; int wkr[2], wnq[2], wmat[2];
#pragma unroll
    for (int i = 0; i < 2; i++) {
        int c = tid + i * 256;
        int mat = c >> 8, rem = c & 255, kr = rem >> 4, nq = rem & 15;
        const float* W = mat ? Wu : Wg;
        gW[i] = W + ((size_t)e * DIM + kr) * MDIM + n0 + nq * 4;
        soW[i] = 24576u + mat * 4096 + kr * 256 + nq * 16;
        wkr[i] = kr; wnq[i] = nq; wmat[i] = mat;
    }

    float accG[2][4][4] = {}, accU[2][4][4] = {};
    uint32_t aOff = (wm0 + (lane & 15)) * 48 + (lane >> 4) * 16;
    // FIX: include sb in the B ldmatrix base address
    uint32_t bOff = sb + 32768u + ((lane & 7) + ((lane >> 4) & 1) * 8 + wn0) * 48
                  + ((lane >> 3) & 1) * 16;

#pragma unroll
    for (int i = 0; i < 2; i++) { cpasync16(sb + soA[i], gA[i]); cpasync16(sb + soW[i], gW[i]); }
    CP_COMMIT();

    const int NCH = DIM / 16;  // 128
    for (int kc = 0; kc < NCH; kc++) {
        int st = kc & 1;
        CP_WAIT0();
        __syncthreads();
#pragma unroll
        for (int i = 0; i < 2; i++) {
            float4 v = *(const float4*)(smem + soW[i]);
            char* bh = smem + 32768 + wmat[i] * 6144;
            int kb = wkr[i] * 2;
#pragma unroll
            for (int j = 0; j < 4; j++) {
                float f = (&v.x)[j];
                __nv_bfloat16 h, l;
                split2(f, h, l);
                int n_ = wnq[i] * 4 + j;
                *(__nv_bfloat16*)(bh + n_ * 48 + kb) = h;
                *(__nv_bfloat16*)(bh + 3072 + n_ * 48 + kb) = l;
            }
        }
        __syncthreads();
        if (kc + 1 < NCH) {
#pragma unroll
            for (int i = 0; i < 2; i++) {
                cpasync16(sb + (st ^ 1) * 12288 + soA[i], gA[i] + (kc + 1) * 16);
                cpasync16(sb + soW[i], gW[i] + (size_t)(kc + 1) * 16 * MDIM);
            }
            CP_COMMIT();
        }
        uint32_t aA = sb + st * 12288 + aOff;
        uint32_t aH0[4], aH1[4], aL0[4], aL1[4], b[4], b2[4];
        LDSM4(aH0, aA); LDSM4(aH1, aA + 768);
        LDSM4(aL0, aA + 6144); LDSM4(aL1, aA + 6912);
        LDSM4(b, bOff); LDSM4(b2, bOff + 768);
        MMA8(accG, aH0, aH1, b, b2);
        MMA8(accG, aL0, aL1, b, b2);
        LDSM4(b, bOff + 3072); LDSM4(b2, bOff + 3840);
        MMA8(accG, aH0, aH1, b, b2);
        LDSM4(b, bOff + 6144); LDSM4(b2, bOff + 6912);
        MMA8(accU, aH0, aH1, b, b2);
        MMA8(accU, aL0, aL1, b, b2);
        LDSM4(b, bOff + 9216); LDSM4(b2, bOff + 9984);
        MMA8(accU, aH0, aH1, b, b2);
        __syncthreads();
    }

#pragma unroll
    for (int f = 0; f < 2; f++) {
        int rl = row0 + wm0 + f * 16 + (lane >> 2);
        int rh = rl + 8;
#pragma unroll
        for (int j = 0; j < 4; j++) {
            int c = n0 + wn0 + j * 8 + (lane & 3) * 2;
            float g0 = accG[f][j][0], g1 = accG[f][j][1];
            float g2 = accG[f][j][2], g3 = accG[f][j][3];
            float u0 = accU[f][j][0], u1 = accU[f][j][1];
            float u2 = accU[f][j][2], u3 = accU[f][j][3];
            float v0 = (g0 / (1.f + __expf(-g0))) * u0;
            float v1 = (g1 / (1.f + __expf(-g1))) * u1;
            float v2 = (g2 / (1.f + __expf(-g2))) * u2;
            float v3 = (g3 / (1.f + __expf(-g3))) * u3;
            __nv_bfloat16 h0, l0, h1, l1, h2, l2, h3, l3;
            split2(v0, h0, l0); split2(v1, h1, l1);
            split2(v2, h2, l2); split2(v3, h3, l3);
            if (rl < row_end) {
                *(uint32_t*)(g_Ih + (size_t)rl * MDIM + c) = pack2(h0, h1);
                *(uint32_t*)(g_Il + (size_t)rl * MDIM + c) = pack2(l0, l1);
            }
            if (rh < row_end) {
                *(uint32_t*)(g_Ih + (size_t)rh * MDIM + c) = pack2(h2, h3);
                *(uint32_t*)(g_Il + (size_t)rh * MDIM + c) = pack2(l2, l3);
            }
        }
    }
}

// ============ GEMM2: down proj ============
__global__ __launch_bounds__(256) void k_gemm2(const float* __restrict__ Wd) {
    int mt = blockIdx.y;
    if (mt >= g_num_tiles) return;
    int e = g_tile_expert[mt], row0 = g_tile_row[mt], row_end = g_off[e + 1];
    int n0 = blockIdx.x * 64;

    __shared__ __align__(128) char smem[34816];
    uint32_t sb = smem_u32(smem);
    int tid = threadIdx.x, wid = tid >> 5, lane = tid & 31;
    int wm0 = (wid >> 1) * 32, wn0 = (wid & 1) * 32;

    const __nv_bfloat16* gA[2]; uint32_t soA[2];
#pragma unroll
    for (int i = 0; i < 2; i++) {
        int c = tid + i * 256;
        int half = c >> 8, rem = c & 255, row = rem >> 1, q = rem & 1;
        int gr = row0 + row; if (gr > NROWS - 1) gr = NROWS - 1;
        gA[i] = (half ? g_Il : g_Ih) + (size_t)gr * MDIM + q * 8;
        soA[i] = half * 6144 + row * 48 + q * 16;
    }
    int kr = tid >> 4, nq = tid & 15;
    const float* gW = Wd + ((size_t)e * MDIM + kr) * DIM + n0 + nq * 4;
    uint32_t soW = 24576u + kr * 256 + nq * 16;

    float acc[2][4][4] = {};
    uint32_t aOff = (wm0 + (lane & 15)) * 48 + (lane >> 4) * 16;
    // FIX: include sb
    uint32_t bOff = sb + 28672u + ((lane & 7) + ((lane >> 4) & 1) * 8 + wn0) * 48
                  + ((lane >> 3) & 1) * 16;

#pragma unroll
    for (int i = 0; i < 2; i++) cpasync16(sb + soA[i], gA[i]);
    cpasync16(sb + soW, gW);
    CP_COMMIT();

    const int NCH = MDIM / 16;  // 48
    for (int kc = 0; kc < NCH; kc++) {
        int st = kc & 1;
        CP_WAIT0();
        __syncthreads();
        {
            float4 v = *(const float4*)(smem + soW);
            char* bh = smem + 28672;
            int kb = kr * 2;
#pragma unroll
            for (int j = 0; j < 4; j++) {
                float f = (&v.x)[j];
                __nv_bfloat16 h, l;
                split2(f, h, l);
                int n_ = nq * 4 + j;
                *(__nv_bfloat16*)(bh + n_ * 48 + kb) = h;
                *(__nv_bfloat16*)(bh + 3072 + n_ * 48 + kb) = l;
            }
        }
        __syncthreads();
        if (kc + 1 < NCH) {
#pragma unroll
            for (int i = 0; i < 2; i++)
                cpasync16(sb + (st ^ 1) * 12288 + soA[i], gA[i] + (kc + 1) * 16);
            cpasync16(sb + soW, gW + (size_t)(kc + 1) * 16 * DIM);
            CP_COMMIT();
        }
        uint32_t aA = sb + st * 12288 + aOff;
        uint32_t aH0[4], aH1[4], aL0[4], aL1[4], b[4], b2[4];
        LDSM4(aH0, aA); LDSM4(aH1, aA + 768);
        LDSM4(aL0, aA + 6144); LDSM4(aL1, aA + 6912);
        LDSM4(b, bOff); LDSM4(b2, bOff + 768);
        MMA8(acc, aH0, aH1, b, b2);
        MMA8(acc, aL0, aL1, b, b2);
        LDSM4(b, bOff + 3072); LDSM4(b2, bOff + 3840);
        MMA8(acc, aH0, aH1, b, b2);
        __syncthreads();
    }

#pragma unroll
    for (int f = 0; f < 2; f++) {
        int rl = row0 + wm0 + f * 16 + (lane >> 2);
        int rh = rl + 8;
#pragma unroll
        for (int j = 0; j < 4; j++) {
            int c = n0 + wn0 + j * 8 + (lane & 3) * 2;
            if (rl < row_end)
                *(float2*)(g_eout + (size_t)rl * DIM + c) = make_float2(acc[f][j][0], acc[f][j][1]);
            if (rh < row_end)
                *(float2*)(g_eout + (size_t)rh * DIM + c) = make_float2(acc[f][j][2], acc[f][j][3]);
        }
    }
}

// ============ combine ============
__global__ __launch_bounds__(256) void k_combine(float* __restrict__ out) {
    int t = blockIdx.x;
    __shared__ float w[TOPK];
    __shared__ int   ps[TOPK];
    if (threadIdx.x < TOPK) {
        w[threadIdx.x]  = g_weight_of[t * TOPK + threadIdx.x];
        ps[threadIdx.x] = g_pos_of[t * TOPK + threadIdx.x];
    }
    __syncthreads();
    for (int d = threadIdx.x; d < DIM; d += 256) {
        float s = 0.f;
#pragma unroll
        for (int k = 0; k < TOPK; k++)
            s += w[k] * g_eout[(size_t)ps[k] * DIM + d];
        out[(size_t)t * DIM + d] = s;
    }
}

// ============ launch ============
extern "C" void kernel_launch(void* const* d_in, const int* in_sizes, int n_in,
                              void* d_out, int out_size) {
    const float* x  = (const float*)d_in[0];
    const float* gk = (const float*)d_in[1];
    const float* wg = (const float*)d_in[2];
    const float* wu = (const float*)d_in[3];
    const float* wd = (const float*)d_in[4];
    float* out = (float*)d_out;

    k_init<<<1, 32>>>();
    k_router<<<TOKENS / 64, 256>>>(x, gk);
    k_prefix<<<1, 32>>>();
    k_scatter<<<NROWS / 256, 256>>>();
    k_convert_x<<<TOKENS, 256>>>(x);
    k_gemm1<<<dim3(MDIM / 64, MAX_TILES), 256>>>(wg, wu);
    k_gemm2<<<dim3(DIM / 64, MAX_TILES), 256>>>(wd);
    k_combine<<<TOKENS, 256>>>(out);
}

// round 9
// speedup vs baseline: 1.4422x; 1.1265x over previous
#include <cuda_runtime.h>
#include <cuda_bf16.h>
#include <stdint.h>
#include <math.h>

#define TOKENS 4096
#define DIM    2048
#define NEXP   32
#define TOPK   8
#define MDIM   768
#define NROWS  (TOKENS*TOPK)
#define BM     128
#define MAX_TILES 288

__device__ __forceinline__ uint32_t smem_u32(const void* p) {
    uint32_t a;
    asm("{ .reg .u64 t; cvta.to.shared.u64 t, %1; cvt.u32.u64 %0, t; }" : "=r"(a) : "l"(p));
    return a;
}
__device__ __forceinline__ void cpasync16(uint32_t s, const void* g) {
    asm volatile("cp.async.cg.shared.global [%0], [%1], 16;" :: "r"(s), "l"(g) : "memory");
}
#define CP_COMMIT() asm volatile("cp.async.commit_group;" ::: "memory")
#define CP_WAIT0()  asm volatile("cp.async.wait_group 0;" ::: "memory")

#define LDSM4(r, addr) \
    asm volatile("ldmatrix.sync.aligned.m8n8.x4.shared.b16 {%0,%1,%2,%3}, [%4];" \
        : "=r"((r)[0]), "=r"((r)[1]), "=r"((r)[2]), "=r"((r)[3]) : "r"(addr))

#define MMA_BF16(d, a, b0v, b1v) \
    asm volatile("mma.sync.aligned.m16n8k16.row.col.f32.bf16.bf16.f32 " \
        "{%0,%1,%2,%3},{%4,%5,%6,%7},{%8,%9},{%0,%1,%2,%3};" \
        : "+f"((d)[0]), "+f"((d)[1]), "+f"((d)[2]), "+f"((d)[3]) \
        : "r"((a)[0]), "r"((a)[1]), "r"((a)[2]), "r"((a)[3]), "r"(b0v), "r"(b1v))

#define MMA8(acc, A0, A1, b, b2) do { \
    MMA_BF16(acc[0][0],A0,(b)[0],(b)[1]);  MMA_BF16(acc[0][1],A0,(b)[2],(b)[3]);  \
    MMA_BF16(acc[0][2],A0,(b2)[0],(b2)[1]);MMA_BF16(acc[0][3],A0,(b2)[2],(b2)[3]);\
    MMA_BF16(acc[1][0],A1,(b)[0],(b)[1]);  MMA_BF16(acc[1][1],A1,(b)[2],(b)[3]);  \
    MMA_BF16(acc[1][2],A1,(b2)[0],(b2)[1]);MMA_BF16(acc[1][3],A1,(b2)[2],(b2)[3]);\
} while(0)

__device__ __forceinline__ void split2(float v, __nv_bfloat16& h, __nv_bfloat16& l) {
    h = __float2bfloat16(v);
    l = __float2bfloat16(v - __bfloat162float(h));
}
__device__ __forceinline__ uint32_t pack2(__nv_bfloat16 a, __nv_bfloat16 b) {
    __nv_bfloat162 t(a, b);
    return *(uint32_t*)&t;
}

// ============ device scratch (~402MB, R7-proven budget) ============
__device__ int   g_cnt[NEXP];
__device__ int   g_off[NEXP + 1];
__device__ int   g_cursor[NEXP];
__device__ int   g_expert_of[NROWS];
__device__ float g_weight_of[NROWS];
__device__ int   g_row_token[NROWS];
__device__ int   g_pos_of[NROWS];
__device__ int   g_tile_expert[MAX_TILES];
__device__ int   g_tile_row[MAX_TILES];
__device__ int   g_num_tiles;
__device__ __nv_bfloat16 g_Xh[(size_t)TOKENS * DIM];
__device__ __nv_bfloat16 g_Xl[(size_t)TOKENS * DIM];
__device__ __nv_bfloat16 g_Ih[(size_t)NROWS * MDIM];
__device__ __nv_bfloat16 g_Il[(size_t)NROWS * MDIM];
__device__ float g_eout[(size_t)NROWS * DIM];

// ============ routing (proven) ============
__global__ void k_init() {
    int i = threadIdx.x;
    if (i < NEXP) { g_cnt[i] = 0; g_cursor[i] = 0; }
}

__global__ __launch_bounds__(256) void k_router(const float* __restrict__ x,
                                                const float* __restrict__ gk) {
    __shared__ float xs[64][64];
    __shared__ float gs[64][32];
    __shared__ float lg[64][32];
    int tid = threadIdx.x, t0 = blockIdx.x * 64, e = tid & 31, r8 = tid >> 5;
    float acc[8];
#pragma unroll
    for (int i = 0; i < 8; i++) acc[i] = 0.f;
    for (int d0 = 0; d0 < DIM; d0 += 64) {
#pragma unroll
        for (int i = 0; i < 4; i++) {
            int f = tid + i * 256, row = f >> 4, dv = f & 15;
            *(float4*)&xs[row][dv * 4] =
                *(const float4*)(x + (size_t)(t0 + row) * DIM + d0 + dv * 4);
        }
#pragma unroll
        for (int i = 0; i < 2; i++) {
            int f = tid + i * 256, dd = f >> 3, ev = f & 7;
            *(float4*)&gs[dd][ev * 4] =
                *(const float4*)(gk + (size_t)(d0 + dd) * NEXP + ev * 4);
        }
        __syncthreads();
#pragma unroll 8
        for (int dd = 0; dd < 64; dd++) {
            float g = gs[dd][e];
#pragma unroll
            for (int rr = 0; rr < 8; rr++) acc[rr] += xs[rr * 8 + r8][dd] * g;
        }
        __syncthreads();
    }
#pragma unroll
    for (int rr = 0; rr < 8; rr++) lg[rr * 8 + r8][e] = acc[rr];
    __syncthreads();

    int w = tid >> 5, lane = tid & 31;
    for (int ti = 0; ti < 8; ti++) {
        int tok = w * 8 + ti;
        float logit = lg[tok][lane];
        unsigned selmask = 0;
        float vals[TOPK]; int ids[TOPK];
#pragma unroll
        for (int k = 0; k < TOPK; k++) {
            float v = ((selmask >> lane) & 1u) ? -1e30f : logit;
            float bv = v; int bi = lane;
#pragma unroll
            for (int off = 16; off; off >>= 1) {
                float ov = __shfl_down_sync(0xffffffffu, bv, off);
                int   oi = __shfl_down_sync(0xffffffffu, bi, off);
                if (ov > bv || (ov == bv && oi < bi)) { bv = ov; bi = oi; }
            }
            bv = __shfl_sync(0xffffffffu, bv, 0);
            bi = __shfl_sync(0xffffffffu, bi, 0);
            vals[k] = bv; ids[k] = bi;
            selmask |= 1u << bi;
        }
        if (lane == 0) {
            float mx = vals[0], s = 0.f, wv[TOPK];
#pragma unroll
            for (int k = 0; k < TOPK; k++) { wv[k] = expf(vals[k] - mx); s += wv[k]; }
            float inv = 1.f / s;
            int t = t0 + tok;
#pragma unroll
            for (int k = 0; k < TOPK; k++) {
                g_weight_of[t * TOPK + k] = wv[k] * inv;
                g_expert_of[t * TOPK + k] = ids[k];
                atomicAdd(&g_cnt[ids[k]], 1);
            }
        }
    }
}

__global__ void k_prefix() {
    int lane = threadIdx.x;
    int c = (lane < NEXP) ? g_cnt[lane] : 0;
    int s = c;
#pragma unroll
    for (int off = 1; off < 32; off <<= 1) {
        int v = __shfl_up_sync(0xffffffffu, s, off);
        if (lane >= off) s += v;
    }
    if (lane < NEXP) g_off[lane + 1] = s;
    if (lane == 0) {
        g_off[0] = 0;
        int nt = 0, base = 0;
        for (int e = 0; e < NEXP; e++) {
            int cc = g_cnt[e];
            for (int r = 0; r < cc; r += BM) {
                g_tile_expert[nt] = e;
                g_tile_row[nt] = base + r;
                nt++;
            }
            base += cc;
        }
        g_num_tiles = nt;
    }
}

__global__ void k_scatter() {
    int i = blockIdx.x * blockDim.x + threadIdx.x;
    if (i >= NROWS) return;
    int e = g_expert_of[i];
    int p = g_off[e] + atomicAdd(&g_cursor[e], 1);
    g_row_token[p] = i >> 3;
    g_pos_of[i] = p;
}

// ============ token fp32 -> split bf16 ============
__global__ __launch_bounds__(256) void k_convert_x(const float* __restrict__ x) {
    int t = blockIdx.x;
    const float4* src = (const float4*)(x + (size_t)t * DIM);
#pragma unroll
    for (int i = 0; i < 2; i++) {
        int idx = threadIdx.x + i * 256;
        float4 v = src[idx];
        __nv_bfloat16 h0, h1, h2, h3, l0, l1, l2, l3;
        split2(v.x, h0, l0); split2(v.y, h1, l1);
        split2(v.z, h2, l2); split2(v.w, h3, l3);
        *(uint2*)(g_Xh + (size_t)t * DIM + idx * 4) = make_uint2(pack2(h0, h1), pack2(h2, h3));
        *(uint2*)(g_Xl + (size_t)t * DIM + idx * 4) = make_uint2(pack2(l0, l1), pack2(l2, l3));
    }
}

// ============ GEMM1: gate+up, reg-based W convert, 2 syncs/chunk ============
// smem: A 2 stages x (Ah 6144 + Al 6144) @0..24576 (48B rows)
//       B bf16 single: gh@24576 gl@27648 uh@30720 ul@33792 ; total 36864
__global__ __launch_bounds__(256, 2) void k_gemm1(const float* __restrict__ Wg,
                                                  const float* __restrict__ Wu) {
    int mt = blockIdx.y;
    if (mt >= g_num_tiles) return;
    int e = g_tile_expert[mt], row0 = g_tile_row[mt], row_end = g_off[e + 1];
    int n0 = blockIdx.x * 64;

    __shared__ __align__(128) char smem[36864];
    uint32_t sb = smem_u32(smem);
    int tid = threadIdx.x, wid = tid >> 5, lane = tid & 31;
    int wm0 = (wid >> 1) * 32, wn0 = (wid & 1) * 32;

    // A fill mapping (2 chunks/thread)
    const __nv_bfloat16* gA[2]; uint32_t soA[2];
#pragma unroll
    for (int i = 0; i < 2; i++) {
        int c = tid + i * 256;
        int half = c >> 8, rem = c & 255, row = rem >> 1, q = rem & 1;
        int gr = row0 + row; if (gr > NROWS - 1) gr = NROWS - 1;
        int tok = g_row_token[gr];
        gA[i] = (half ? g_Xl : g_Xh) + (size_t)tok * DIM + q * 8;
        soA[i] = half * 6144 + row * 48 + q * 16;
    }
    // W direct-LDG mapping (2 float4/thread/chunk)
    const float* gW[2]; int wkr[2], wnq[2], wmat[2];
#pragma unroll
    for (int i = 0; i < 2; i++) {
        int c = tid + i * 256;
        int mat = c >> 8, rem = c & 255, kr = rem >> 4, nq = rem & 15;
        const float* W = mat ? Wu : Wg;
        gW[i] = W + ((size_t)e * DIM + kr) * MDIM + n0 + nq * 4;
        wkr[i] = kr; wnq[i] = nq; wmat[i] = mat;
    }

    float accG[2][4][4] = {}, accU[2][4][4] = {};
    uint32_t aOff = (wm0 + (lane & 15)) * 48 + (lane >> 4) * 16;
    uint32_t bOff = sb + 24576u + ((lane & 7) + ((lane >> 4) & 1) * 8 + wn0) * 48
                  + ((lane >> 3) & 1) * 16;

    // prologue: A stage0 via cp.async, W chunk0 into regs
    float4 wreg[2];
#pragma unroll
    for (int i = 0; i < 2; i++) {
        cpasync16(sb + soA[i], gA[i]);
        wreg[i] = *(const float4*)(gW[i]);
    }
    CP_COMMIT();

    const int NCH = DIM / 16;  // 128
    for (int kc = 0; kc < NCH; kc++) {
        int st = kc & 1;
        CP_WAIT0();
        __syncthreads();   // A(kc) visible; all B reads of kc-1 retired
        // prefetch A(kc+1)
        if (kc + 1 < NCH) {
#pragma unroll
            for (int i = 0; i < 2; i++)
                cpasync16(sb + (st ^ 1) * 12288 + soA[i], gA[i] + (kc + 1) * 16);
            CP_COMMIT();
        }
        // convert W(kc) regs -> B bf16 smem
#pragma unroll
        for (int i = 0; i < 2; i++) {
            float4 v = wreg[i];
            char* bh = smem + 24576 + wmat[i] * 6144 + wkr[i] * 2;
#pragma unroll
            for (int j = 0; j < 4; j++) {
                __nv_bfloat16 h, l;
                split2((&v.x)[j], h, l);
                int n_ = wnq[i] * 4 + j;
                *(__nv_bfloat16*)(bh + n_ * 48) = h;
                *(__nv_bfloat16*)(bh + 3072 + n_ * 48) = l;
            }
        }
        // prefetch W(kc+1) into regs
        if (kc + 1 < NCH) {
#pragma unroll
            for (int i = 0; i < 2; i++)
                wreg[i] = *(const float4*)(gW[i] + (size_t)(kc + 1) * 16 * MDIM);
        }
        __syncthreads();   // B bf16 published
        uint32_t aA = sb + st * 12288 + aOff;
        uint32_t aH0[4], aH1[4], aL0[4], aL1[4], b[4], b2[4];
        LDSM4(aH0, aA); LDSM4(aH1, aA + 768);
        LDSM4(aL0, aA + 6144); LDSM4(aL1, aA + 6912);
        LDSM4(b, bOff); LDSM4(b2, bOff + 768);          // gate hi
        MMA8(accG, aH0, aH1, b, b2);
        MMA8(accG, aL0, aL1, b, b2);
        LDSM4(b, bOff + 3072); LDSM4(b2, bOff + 3840);  // gate lo
        MMA8(accG, aH0, aH1, b, b2);
        LDSM4(b, bOff + 6144); LDSM4(b2, bOff + 6912);  // up hi
        MMA8(accU, aH0, aH1, b, b2);
        MMA8(accU, aL0, aL1, b, b2);
        LDSM4(b, bOff + 9216); LDSM4(b2, bOff + 9984);  // up lo
        MMA8(accU, aH0, aH1, b, b2);
    }

    // epilogue: silu(g)*u -> split bf16
#pragma unroll
    for (int f = 0; f < 2; f++) {
        int rl = row0 + wm0 + f * 16 + (lane >> 2);
        int rh = rl + 8;
#pragma unroll
        for (int j = 0; j < 4; j++) {
            int c = n0 + wn0 + j * 8 + (lane & 3) * 2;
            float g0 = accG[f][j][0], g1 = accG[f][j][1];
            float g2 = accG[f][j][2], g3 = accG[f][j][3];
            float u0 = accU[f][j][0], u1 = accU[f][j][1];
            float u2 = accU[f][j][2], u3 = accU[f][j][3];
            float v0 = (g0 / (1.f + __expf(-g0))) * u0;
            float v1 = (g1 / (1.f + __expf(-g1))) * u1;
            float v2 = (g2 / (1.f + __expf(-g2))) * u2;
            float v3 = (g3 / (1.f + __expf(-g3))) * u3;
            __nv_bfloat16 h0, l0, h1, l1, h2, l2, h3, l3;
            split2(v0, h0, l0); split2(v1, h1, l1);
            split2(v2, h2, l2); split2(v3, h3, l3);
            if (rl < row_end) {
                *(uint32_t*)(g_Ih + (size_t)rl * MDIM + c) = pack2(h0, h1);
                *(uint32_t*)(g_Il + (size_t)rl * MDIM + c) = pack2(l0, l1);
            }
            if (rh < row_end) {
                *(uint32_t*)(g_Ih + (size_t)rh * MDIM + c) = pack2(h2, h3);
                *(uint32_t*)(g_Il + (size_t)rh * MDIM + c) = pack2(l2, l3);
            }
        }
    }
}

// ============ GEMM2: down proj, reg-based W convert ============
// smem: A 2 x (h 6144 + l 6144) @0..24576; B bf16: h@24576 l@27648; total 30720
__global__ __launch_bounds__(256, 2) void k_gemm2(const float* __restrict__ Wd) {
    int mt = blockIdx.y;
    if (mt >= g_num_tiles) return;
    int e = g_tile_expert[mt], row0 = g_tile_row[mt], row_end = g_off[e + 1];
    int n0 = blockIdx.x * 64;

    __shared__ __align__(128) char smem[30720];
    uint32_t sb = smem_u32(smem);
    int tid = threadIdx.x, wid = tid >> 5, lane = tid & 31;
    int wm0 = (wid >> 1) * 32, wn0 = (wid & 1) * 32;

    const __nv_bfloat16* gA[2]; uint32_t soA[2];
#pragma unroll
    for (int i = 0; i < 2; i++) {
        int c = tid + i * 256;
        int half = c >> 8, rem = c & 255, row = rem >> 1, q = rem & 1;
        int gr = row0 + row; if (gr > NROWS - 1) gr = NROWS - 1;
        gA[i] = (half ? g_Il : g_Ih) + (size_t)gr * MDIM + q * 8;
        soA[i] = half * 6144 + row * 48 + q * 16;
    }
    int kr = tid >> 4, nq = tid & 15;
    const float* gW = Wd + ((size_t)e * MDIM + kr) * DIM + n0 + nq * 4;

    float acc[2][4][4] = {};
    uint32_t aOff = (wm0 + (lane & 15)) * 48 + (lane >> 4) * 16;
    uint32_t bOff = sb + 24576u + ((lane & 7) + ((lane >> 4) & 1) * 8 + wn0) * 48
                  + ((lane >> 3) & 1) * 16;

    float4 wreg;
#pragma unroll
    for (int i = 0; i < 2; i++) cpasync16(sb + soA[i], gA[i]);
    wreg = *(const float4*)(gW);
    CP_COMMIT();

    const int NCH = MDIM / 16;  // 48
    for (int kc = 0; kc < NCH; kc++) {
        int st = kc & 1;
        CP_WAIT0();
        __syncthreads();
        if (kc + 1 < NCH) {
#pragma unroll
            for (int i = 0; i < 2; i++)
                cpasync16(sb + (st ^ 1) * 12288 + soA[i], gA[i] + (kc + 1) * 16);
            CP_COMMIT();
        }
        {
            float4 v = wreg;
            char* bh = smem + 24576 + kr * 2;
#pragma unroll
            for (int j = 0; j < 4; j++) {
                __nv_bfloat16 h, l;
                split2((&v.x)[j], h, l);
                int n_ = nq * 4 + j;
                *(__nv_bfloat16*)(bh + n_ * 48) = h;
                *(__nv_bfloat16*)(bh + 3072 + n_ * 48) = l;
            }
        }
        if (kc + 1 < NCH)
            wreg = *(const float4*)(gW + (size_t)(kc + 1) * 16 * DIM);
        __syncthreads();
        uint32_t aA = sb + st * 12288 + aOff;
        uint32_t aH0[4], aH1[4], aL0[4], aL1[4], b[4], b2[4];
        LDSM4(aH0, aA); LDSM4(aH1, aA + 768);
        LDSM4(aL0, aA + 6144); LDSM4(aL1, aA + 6912);
        LDSM4(b, bOff); LDSM4(b2, bOff + 768);
        MMA8(acc, aH0, aH1, b, b2);
        MMA8(acc, aL0, aL1, b, b2);
        LDSM4(b, bOff + 3072); LDSM4(b2, bOff + 3840);
        MMA8(acc, aH0, aH1, b, b2);
    }

#pragma unroll
    for (int f = 0; f < 2; f++) {
        int rl = row0 + wm0 + f * 16 + (lane >> 2);
        int rh = rl + 8;
#pragma unroll
        for (int j = 0; j < 4; j++) {
            int c = n0 + wn0 + j * 8 + (lane & 3) * 2;
            if (rl < row_end)
                *(float2*)(g_eout + (size_t)rl * DIM + c) = make_float2(acc[f][j][0], acc[f][j][1]);
            if (rh < row_end)
                *(float2*)(g_eout + (size_t)rh * DIM + c) = make_float2(acc[f][j][2], acc[f][j][3]);
        }
    }
}

// ============ combine ============
__global__ __launch_bounds__(256) void k_combine(float* __restrict__ out) {
    int t = blockIdx.x;
    __shared__ float w[TOPK];
    __shared__ int   ps[TOPK];
    if (threadIdx.x < TOPK) {
        w[threadIdx.x]  = g_weight_of[t * TOPK + threadIdx.x];
        ps[threadIdx.x] = g_pos_of[t * TOPK + threadIdx.x];
    }
    __syncthreads();
    for (int d = threadIdx.x; d < DIM; d += 256) {
        float s = 0.f;
#pragma unroll
        for (int k = 0; k < TOPK; k++)
            s += w[k] * g_eout[(size_t)ps[k] * DIM + d];
        out[(size_t)t * DIM + d] = s;
    }
}

// ============ launch ============
extern "C" void kernel_launch(void* const* d_in, const int* in_sizes, int n_in,
                              void* d_out, int out_size) {
    const float* x  = (const float*)d_in[0];
    const float* gk = (const float*)d_in[1];
    const float* wg = (const float*)d_in[2];
    const float* wu = (const float*)d_in[3];
    const float* wd = (const float*)d_in[4];
    float* out = (float*)d_out;

    k_init<<<1, 32>>>();
    k_router<<<TOKENS / 64, 256>>>(x, gk);
    k_prefix<<<1, 32>>>();
    k_scatter<<<NROWS / 256, 256>>>();
    k_convert_x<<<TOKENS, 256>>>(x);
    k_gemm1<<<dim3(MDIM / 64, MAX_TILES), 256>>>(wg, wu);
    k_gemm2<<<dim3(DIM / 64, MAX_TILES), 256>>>(wd);
    k_combine<<<TOKENS, 256>>>(out);
}

// round 10
// speedup vs baseline: 2.3775x; 1.6485x over previous
#include <cuda_runtime.h>
#include <cuda_bf16.h>
#include <stdint.h>
#include <math.h>

#define TOKENS 4096
#define DIM    2048
#define NEXP   32
#define TOPK   8
#define MDIM   768
#define NROWS  (TOKENS*TOPK)
#define BM     128
#define MAX_TILES 288

__device__ __forceinline__ uint32_t smem_u32(const void* p) {
    uint32_t a;
    asm("{ .reg .u64 t; cvta.to.shared.u64 t, %1; cvt.u32.u64 %0, t; }" : "=r"(a) : "l"(p));
    return a;
}
__device__ __forceinline__ void cpasync16(uint32_t s, const void* g) {
    asm volatile("cp.async.cg.shared.global [%0], [%1], 16;" :: "r"(s), "l"(g) : "memory");
}
#define CP_COMMIT() asm volatile("cp.async.commit_group;" ::: "memory")
#define CP_WAIT0()  asm volatile("cp.async.wait_group 0;" ::: "memory")

#define LDSM4(r, addr) \
    asm volatile("ldmatrix.sync.aligned.m8n8.x4.shared.b16 {%0,%1,%2,%3}, [%4];" \
        : "=r"((r)[0]), "=r"((r)[1]), "=r"((r)[2]), "=r"((r)[3]) : "r"(addr))

#define LDSM4T(r, addr) \
    asm volatile("ldmatrix.sync.aligned.m8n8.x4.trans.shared.b16 {%0,%1,%2,%3}, [%4];" \
        : "=r"((r)[0]), "=r"((r)[1]), "=r"((r)[2]), "=r"((r)[3]) : "r"(addr))

#define MMA_BF16(d, a, b0v, b1v) \
    asm volatile("mma.sync.aligned.m16n8k16.row.col.f32.bf16.bf16.f32 " \
        "{%0,%1,%2,%3},{%4,%5,%6,%7},{%8,%9},{%0,%1,%2,%3};" \
        : "+f"((d)[0]), "+f"((d)[1]), "+f"((d)[2]), "+f"((d)[3]) \
        : "r"((a)[0]), "r"((a)[1]), "r"((a)[2]), "r"((a)[3]), "r"(b0v), "r"(b1v))

// 4 MMAs: two A row-halves x two n-groups from one LDSM4T
#define MMA4(acc, j0, A0, A1, b) do { \
    MMA_BF16(acc[0][j0],   A0, (b)[0], (b)[1]); \
    MMA_BF16(acc[0][j0+1], A0, (b)[2], (b)[3]); \
    MMA_BF16(acc[1][j0],   A1, (b)[0], (b)[1]); \
    MMA_BF16(acc[1][j0+1], A1, (b)[2], (b)[3]); \
} while(0)

__device__ __forceinline__ void split2(float v, __nv_bfloat16& h, __nv_bfloat16& l) {
    h = __float2bfloat16(v);
    l = __float2bfloat16(v - __bfloat162float(h));
}
__device__ __forceinline__ uint32_t pack2(__nv_bfloat16 a, __nv_bfloat16 b) {
    __nv_bfloat162 t(a, b);
    return *(uint32_t*)&t;
}
// split float4 -> packed h (uint2) and l (uint2)
__device__ __forceinline__ void split4pack(float4 v, uint2& hh, uint2& ll) {
    __nv_bfloat16 h0, h1, h2, h3, l0, l1, l2, l3;
    split2(v.x, h0, l0); split2(v.y, h1, l1);
    split2(v.z, h2, l2); split2(v.w, h3, l3);
    hh = make_uint2(pack2(h0, h1), pack2(h2, h3));
    ll = make_uint2(pack2(l0, l1), pack2(l2, l3));
}

// ============ device scratch (~402MB, proven budget) ============
__device__ int   g_off[NEXP + 1];
__device__ int   g_expert_of[NROWS];
__device__ float g_weight_of[NROWS];
__device__ int   g_row_token[NROWS];
__device__ int   g_pos_of[NROWS];
__device__ int   g_tile_expert[MAX_TILES];
__device__ int   g_tile_row[MAX_TILES];
__device__ int   g_num_tiles;
__device__ __nv_bfloat16 g_Xh[(size_t)TOKENS * DIM];
__device__ __nv_bfloat16 g_Xl[(size_t)TOKENS * DIM];
__device__ __nv_bfloat16 g_Ih[(size_t)NROWS * MDIM];
__device__ __nv_bfloat16 g_Il[(size_t)NROWS * MDIM];
__device__ float g_eout[(size_t)NROWS * DIM];

// ============ token fp32 -> split bf16 (launch #1) ============
__global__ __launch_bounds__(256) void k_convert_x(const float* __restrict__ x) {
    int t = blockIdx.x;
    const float4* src = (const float4*)(x + (size_t)t * DIM);
#pragma unroll
    for (int i = 0; i < 2; i++) {
        int idx = threadIdx.x + i * 256;
        uint2 hh, ll;
        split4pack(src[idx], hh, ll);
        *(uint2*)(g_Xh + (size_t)t * DIM + idx * 4) = hh;
        *(uint2*)(g_Xl + (size_t)t * DIM + idx * 4) = ll;
    }
}

// ============ router (launch #2; no global counters) ============
__global__ __launch_bounds__(256) void k_router(const float* __restrict__ x,
                                                const float* __restrict__ gk) {
    __shared__ float xs[64][64];
    __shared__ float gs[64][32];
    __shared__ float lg[64][32];
    int tid = threadIdx.x, t0 = blockIdx.x * 64, e = tid & 31, r8 = tid >> 5;
    float acc[8];
#pragma unroll
    for (int i = 0; i < 8; i++) acc[i] = 0.f;
    for (int d0 = 0; d0 < DIM; d0 += 64) {
#pragma unroll
        for (int i = 0; i < 4; i++) {
            int f = tid + i * 256, row = f >> 4, dv = f & 15;
            *(float4*)&xs[row][dv * 4] =
                *(const float4*)(x + (size_t)(t0 + row) * DIM + d0 + dv * 4);
        }
#pragma unroll
        for (int i = 0; i < 2; i++) {
            int f = tid + i * 256, dd = f >> 3, ev = f & 7;
            *(float4*)&gs[dd][ev * 4] =
                *(const float4*)(gk + (size_t)(d0 + dd) * NEXP + ev * 4);
        }
        __syncthreads();
#pragma unroll 8
        for (int dd = 0; dd < 64; dd++) {
            float g = gs[dd][e];
#pragma unroll
            for (int rr = 0; rr < 8; rr++) acc[rr] += xs[rr * 8 + r8][dd] * g;
        }
        __syncthreads();
    }
#pragma unroll
    for (int rr = 0; rr < 8; rr++) lg[rr * 8 + r8][e] = acc[rr];
    __syncthreads();

    int w = tid >> 5, lane = tid & 31;
    for (int ti = 0; ti < 8; ti++) {
        int tok = w * 8 + ti;
        float logit = lg[tok][lane];
        unsigned selmask = 0;
        float vals[TOPK]; int ids[TOPK];
#pragma unroll
        for (int k = 0; k < TOPK; k++) {
            float v = ((selmask >> lane) & 1u) ? -1e30f : logit;
            float bv = v; int bi = lane;
#pragma unroll
            for (int off = 16; off; off >>= 1) {
                float ov = __shfl_down_sync(0xffffffffu, bv, off);
                int   oi = __shfl_down_sync(0xffffffffu, bi, off);
                if (ov > bv || (ov == bv && oi < bi)) { bv = ov; bi = oi; }
            }
            bv = __shfl_sync(0xffffffffu, bv, 0);
            bi = __shfl_sync(0xffffffffu, bi, 0);
            vals[k] = bv; ids[k] = bi;
            selmask |= 1u << bi;
        }
        if (lane == 0) {
            float mx = vals[0], s = 0.f, wv[TOPK];
#pragma unroll
            for (int k = 0; k < TOPK; k++) { wv[k] = expf(vals[k] - mx); s += wv[k]; }
            float inv = 1.f / s;
            int t = t0 + tok;
#pragma unroll
            for (int k = 0; k < TOPK; k++) {
                g_weight_of[t * TOPK + k] = wv[k] * inv;
                g_expert_of[t * TOPK + k] = ids[k];
            }
        }
    }
}

// ============ fused histogram + prefix + tile map + scatter (launch #3) ============
__global__ __launch_bounds__(1024) void k_prefix_scatter() {
    __shared__ int cnt[NEXP], off_s[NEXP + 1], cur[NEXP];
    int tid = threadIdx.x;
    if (tid < NEXP) { cnt[tid] = 0; cur[tid] = 0; }
    __syncthreads();
    for (int i = tid; i < NROWS; i += 1024)
        atomicAdd(&cnt[g_expert_of[i]], 1);
    __syncthreads();
    if (tid < 32) {
        int c = (tid < NEXP) ? cnt[tid] : 0;
        int s = c;
#pragma unroll
        for (int off = 1; off < 32; off <<= 1) {
            int v = __shfl_up_sync(0xffffffffu, s, off);
            if (tid >= off) s += v;
        }
        if (tid < NEXP) off_s[tid + 1] = s;
        if (tid == 0) off_s[0] = 0;
    }
    __syncthreads();
    if (tid <= NEXP) g_off[tid] = off_s[tid];
    if (tid == 0) {
        int nt = 0;
        for (int e = 0; e < NEXP; e++) {
            int cc = cnt[e], base = off_s[e];
            for (int r = 0; r < cc; r += BM) {
                g_tile_expert[nt] = e;
                g_tile_row[nt] = base + r;
                nt++;
            }
        }
        g_num_tiles = nt;
    }
    for (int i = tid; i < NROWS; i += 1024) {
        int e = g_expert_of[i];
        int p = off_s[e] + atomicAdd(&cur[e], 1);
        g_row_token[p] = i >> 3;
        g_pos_of[i] = p;
    }
}

// ============ GEMM1 (launch #4): gate+up, 128M x 128N, trans-B, reg W convert ============
// smem: A 2 stages x (Ah 6144 + Al 6144) @0..24576 (48B rows, conflict-free)
//       B k-major (16 x 272B rows): gh@24576 gl@28928 uh@33280 ul@37632 ; total 41984
__global__ __launch_bounds__(256, 1) void k_gemm1(const float* __restrict__ Wg,
                                                  const float* __restrict__ Wu) {
    int mt = blockIdx.y;
    if (mt >= g_num_tiles) return;
    int e = g_tile_expert[mt], row0 = g_tile_row[mt], row_end = g_off[e + 1];
    int n0 = blockIdx.x * 128;

    __shared__ __align__(128) char smem[41984];
    uint32_t sb = smem_u32(smem);
    int tid = threadIdx.x, wid = tid >> 5, lane = tid & 31;
    int wm0 = (wid >> 1) * 32, wn0 = (wid & 1) * 64;

    // A fill mapping (2 chunks/thread)
    const __nv_bfloat16* gA[2]; uint32_t soA[2];
#pragma unroll
    for (int i = 0; i < 2; i++) {
        int c = tid + i * 256;
        int half = c >> 8, rem = c & 255, row = rem >> 1, q = rem & 1;
        int gr = row0 + row; if (gr > NROWS - 1) gr = NROWS - 1;
        int tok = g_row_token[gr];
        gA[i] = (half ? g_Xl : g_Xh) + (size_t)tok * DIM + q * 8;
        soA[i] = half * 6144 + row * 48 + q * 16;
    }
    // W direct-LDG mapping: 4 float4/thread/chunk (16k x 128n x 2 mats)
    const float* gW[4]; int wkr[4], wnq[4], wmat[4];
#pragma unroll
    for (int i = 0; i < 4; i++) {
        int c = tid + i * 256;
        int mat = c >> 9, rem = c & 511, kr = rem >> 5, nq = rem & 31;
        const float* W = mat ? Wu : Wg;
        gW[i] = W + ((size_t)e * DIM + kr) * MDIM + n0 + nq * 4;
        wkr[i] = kr; wnq[i] = nq; wmat[i] = mat;
    }

    float accG[2][8][4] = {}, accU[2][8][4] = {};
    uint32_t aOff = (wm0 + (lane & 15)) * 48 + (lane >> 4) * 16;
    // trans-B lane address: k_row in 0..15, +16B for n+8 half, + warp n base
    uint32_t bT = ((lane & 7) + ((lane >> 3) & 1) * 8) * 272
                + ((lane >> 4) & 1) * 16 + wn0 * 2;

    float4 wreg[4];
#pragma unroll
    for (int i = 0; i < 2; i++) cpasync16(sb + soA[i], gA[i]);
#pragma unroll
    for (int i = 0; i < 4; i++) wreg[i] = *(const float4*)(gW[i]);
    CP_COMMIT();

    const int NCH = DIM / 16;  // 128
    for (int kc = 0; kc < NCH; kc++) {
        int st = kc & 1;
        CP_WAIT0();
        __syncthreads();   // A(kc) ready; B(kc-1) reads retired
        if (kc + 1 < NCH) {
#pragma unroll
            for (int i = 0; i < 2; i++)
                cpasync16(sb + (st ^ 1) * 12288 + soA[i], gA[i] + (kc + 1) * 16);
            CP_COMMIT();
        }
        // convert W(kc) regs -> B bf16 (k-major, contiguous 8B stores)
#pragma unroll
        for (int i = 0; i < 4; i++) {
            uint2 hh, ll;
            split4pack(wreg[i], hh, ll);
            char* base = smem + 24576 + wmat[i] * 8704 + wkr[i] * 272 + wnq[i] * 8;
            *(uint2*)base = hh;
            *(uint2*)(base + 4352) = ll;
        }
        if (kc + 1 < NCH) {
#pragma unroll
            for (int i = 0; i < 4; i++)
                wreg[i] = *(const float4*)(gW[i] + (size_t)(kc + 1) * 16 * MDIM);
        }
        __syncthreads();   // B published
        uint32_t aA = sb + st * 12288 + aOff;
        uint32_t aH0[4], aH1[4], aL0[4], aL1[4];
        LDSM4(aH0, aA); LDSM4(aH1, aA + 768);
        LDSM4(aL0, aA + 6144); LDSM4(aL1, aA + 6912);
        uint32_t bb = sb + 24576 + bT;
#pragma unroll
        for (int g = 0; g < 4; g++) {
            uint32_t b[4];
            int j0 = 2 * g;
            LDSM4T(b, bb + g * 32);            // gate hi
            MMA4(accG, j0, aH0, aH1, b);
            MMA4(accG, j0, aL0, aL1, b);
            LDSM4T(b, bb + 4352 + g * 32);     // gate lo (Ah only)
            MMA4(accG, j0, aH0, aH1, b);
            LDSM4T(b, bb + 8704 + g * 32);     // up hi
            MMA4(accU, j0, aH0, aH1, b);
            MMA4(accU, j0, aL0, aL1, b);
            LDSM4T(b, bb + 13056 + g * 32);    // up lo (Ah only)
            MMA4(accU, j0, aH0, aH1, b);
        }
    }

    // epilogue: silu(g)*u -> split bf16
#pragma unroll
    for (int f = 0; f < 2; f++) {
        int rl = row0 + wm0 + f * 16 + (lane >> 2);
        int rh = rl + 8;
#pragma unroll
        for (int j = 0; j < 8; j++) {
            int c = n0 + wn0 + j * 8 + (lane & 3) * 2;
            float g0 = accG[f][j][0], g1 = accG[f][j][1];
            float g2 = accG[f][j][2], g3 = accG[f][j][3];
            float u0 = accU[f][j][0], u1 = accU[f][j][1];
            float u2 = accU[f][j][2], u3 = accU[f][j][3];
            float v0 = (g0 / (1.f + __expf(-g0))) * u0;
            float v1 = (g1 / (1.f + __expf(-g1))) * u1;
            float v2 = (g2 / (1.f + __expf(-g2))) * u2;
            float v3 = (g3 / (1.f + __expf(-g3))) * u3;
            __nv_bfloat16 h0, l0, h1, l1, h2, l2, h3, l3;
            split2(v0, h0, l0); split2(v1, h1, l1);
            split2(v2, h2, l2); split2(v3, h3, l3);
            if (rl < row_end) {
                *(uint32_t*)(g_Ih + (size_t)rl * MDIM + c) = pack2(h0, h1);
                *(uint32_t*)(g_Il + (size_t)rl * MDIM + c) = pack2(l0, l1);
            }
            if (rh < row_end) {
                *(uint32_t*)(g_Ih + (size_t)rh * MDIM + c) = pack2(h2, h3);
                *(uint32_t*)(g_Il + (size_t)rh * MDIM + c) = pack2(l2, l3);
            }
        }
    }
}

// ============ GEMM2 (launch #5): down proj, 128M x 128N ============
// smem: A 2 x (h 6144 + l 6144) @0..24576; B: h@24576 l@28928; total 33280
__global__ __launch_bounds__(256, 2) void k_gemm2(const float* __restrict__ Wd) {
    int mt = blockIdx.y;
    if (mt >= g_num_tiles) return;
    int e = g_tile_expert[mt], row0 = g_tile_row[mt], row_end = g_off[e + 1];
    int n0 = blockIdx.x * 128;

    __shared__ __align__(128) char smem[33280];
    uint32_t sb = smem_u32(smem);
    int tid = threadIdx.x, wid = tid >> 5, lane = tid & 31;
    int wm0 = (wid >> 1) * 32, wn0 = (wid & 1) * 64;

    const __nv_bfloat16* gA[2]; uint32_t soA[2];
#pragma unroll
    for (int i = 0; i < 2; i++) {
        int c = tid + i * 256;
        int half = c >> 8, rem = c & 255, row = rem >> 1, q = rem & 1;
        int gr = row0 + row; if (gr > NROWS - 1) gr = NROWS - 1;
        gA[i] = (half ? g_Il : g_Ih) + (size_t)gr * MDIM + q * 8;
        soA[i] = half * 6144 + row * 48 + q * 16;
    }
    const float* gW[2]; int wkr[2], wnq[2];
#pragma unroll
    for (int i = 0; i < 2; i++) {
        int c = tid + i * 256;
        wkr[i] = c >> 5; wnq[i] = c & 31;
        gW[i] = Wd + ((size_t)e * MDIM + wkr[i]) * DIM + n0 + wnq[i] * 4;
    }

    float acc[2][8][4] = {};
    uint32_t aOff = (wm0 + (lane & 15)) * 48 + (lane >> 4) * 16;
    uint32_t bT = ((lane & 7) + ((lane >> 3) & 1) * 8) * 272
                + ((lane >> 4) & 1) * 16 + wn0 * 2;

    float4 wreg[2];
#pragma unroll
    for (int i = 0; i < 2; i++) { cpasync16(sb + soA[i], gA[i]); wreg[i] = *(const float4*)(gW[i]); }
    CP_COMMIT();

    const int NCH = MDIM / 16;  // 48
    for (int kc = 0; kc < NCH; kc++) {
        int st = kc & 1;
        CP_WAIT0();
        __syncthreads();
        if (kc + 1 < NCH) {
#pragma unroll
            for (int i = 0; i < 2; i++)
                cpasync16(sb + (st ^ 1) * 12288 + soA[i], gA[i] + (kc + 1) * 16);
            CP_COMMIT();
        }
#pragma unroll
        for (int i = 0; i < 2; i++) {
            uint2 hh, ll;
            split4pack(wreg[i], hh, ll);
            char* base = smem + 24576 + wkr[i] * 272 + wnq[i] * 8;
            *(uint2*)base = hh;
            *(uint2*)(base + 4352) = ll;
        }
        if (kc + 1 < NCH) {
#pragma unroll
            for (int i = 0; i < 2; i++)
                wreg[i] = *(const float4*)(gW[i] + (size_t)(kc + 1) * 16 * DIM);
        }
        __syncthreads();
        uint32_t aA = sb + st * 12288 + aOff;
        uint32_t aH0[4], aH1[4], aL0[4], aL1[4];
        LDSM4(aH0, aA); LDSM4(aH1, aA + 768);
        LDSM4(aL0, aA + 6144); LDSM4(aL1, aA + 6912);
        uint32_t bb = sb + 24576 + bT;
#pragma unroll
        for (int g = 0; g < 4; g++) {
            uint32_t b[4];
            int j0 = 2 * g;
            LDSM4T(b, bb + g * 32);            // down hi
            MMA4(acc, j0, aH0, aH1, b);
            MMA4(acc, j0, aL0, aL1, b);
            LDSM4T(b, bb + 4352 + g * 32);     // down lo (Ah only)
            MMA4(acc, j0, aH0, aH1, b);
        }
    }

#pragma unroll
    for (int f = 0; f < 2; f++) {
        int rl = row0 + wm0 + f * 16 + (lane >> 2);
        int rh = rl + 8;
#pragma unroll
        for (int j = 0; j < 8; j++) {
            int c = n0 + wn0 + j * 8 + (lane & 3) * 2;
            if (rl < row_end)
                *(float2*)(g_eout + (size_t)rl * DIM + c) = make_float2(acc[f][j][0], acc[f][j][1]);
            if (rh < row_end)
                *(float2*)(g_eout + (size_t)rh * DIM + c) = make_float2(acc[f][j][2], acc[f][j][3]);
        }
    }
}

// ============ combine (launch #6) ============
__global__ __launch_bounds__(256) void k_combine(float* __restrict__ out) {
    int t = blockIdx.x;
    __shared__ float w[TOPK];
    __shared__ int   ps[TOPK];
    if (threadIdx.x < TOPK) {
        w[threadIdx.x]  = g_weight_of[t * TOPK + threadIdx.x];
        ps[threadIdx.x] = g_pos_of[t * TOPK + threadIdx.x];
    }
    __syncthreads();
    for (int d = threadIdx.x; d < DIM; d += 256) {
        float s = 0.f;
#pragma unroll
        for (int k = 0; k < TOPK; k++)
            s += w[k] * g_eout[(size_t)ps[k] * DIM + d];
        out[(size_t)t * DIM + d] = s;
    }
}

// ============ launch ============
extern "C" void kernel_launch(void* const* d_in, const int* in_sizes, int n_in,
                              void* d_out, int out_size) {
    const float* x  = (const float*)d_in[0];
    const float* gk = (const float*)d_in[1];
    const float* wg = (const float*)d_in[2];
    const float* wu = (const float*)d_in[3];
    const float* wd = (const float*)d_in[4];
    float* out = (float*)d_out;

    k_convert_x<<<TOKENS, 256>>>(x);
    k_router<<<TOKENS / 64, 256>>>(x, gk);
    k_prefix_scatter<<<1, 1024>>>();
    k_gemm1<<<dim3(MDIM / 128, MAX_TILES), 256>>>(wg, wu);
    k_gemm2<<<dim3(DIM / 128, MAX_TILES), 256>>>(wd);
    k_combine<<<TOKENS, 256>>>(out);
}